// round 13
// baseline (speedup 1.0000x reference)
#include <cuda_runtime.h>
#include <cstdint>
#include <cstddef>

// ---------------------------------------------------------------------------
// Problem dims (fixed)
// ---------------------------------------------------------------------------
#define BATCH 64
#define SEQ   2048
#define IND   256
#define UNITS 256
#define M_TOTAL (BATCH * SEQ)          // 131072

typedef unsigned long long ull;

// ---------------------------------------------------------------------------
// Device-global scratch (no runtime allocation allowed)
// ---------------------------------------------------------------------------
__device__ float g_xf[(size_t)M_TOTAL * UNITS];    // 128 MB
__device__ float g_xs[(size_t)M_TOTAL * UNITS];    // 128 MB

// ---------------------------------------------------------------------------
// Packed f32x2 helpers
// ---------------------------------------------------------------------------
__device__ __forceinline__ void fma2(ull& d, ull a, ull b) {
    asm("fma.rn.f32x2 %0, %1, %2, %0;" : "+l"(d) : "l"(a), "l"(b));
}
__device__ __forceinline__ void add2(ull& d, ull a) {
    asm("add.rn.f32x2 %0, %0, %1;" : "+l"(d) : "l"(a));
}
__device__ __forceinline__ ull pack2(float x, float y) {
    ull r;
    asm("mov.b64 %0, {%1, %2};" : "=l"(r)
        : "r"(__float_as_uint(x)), "r"(__float_as_uint(y)));
    return r;
}
__device__ __forceinline__ float2 unpack2(ull v) {
    unsigned lo, hi;
    asm("mov.b64 {%0, %1}, %2;" : "=r"(lo), "=r"(hi) : "l"(v));
    return make_float2(__uint_as_float(lo), __uint_as_float(hi));
}

// ---------------------------------------------------------------------------
// Phase 1: xf = X @ W_f + b_f ; xs = X @ W_s + b_s   (unchanged)
// ---------------------------------------------------------------------------
#define BM 128
#define BN 128
#define BK 16

__global__ __launch_bounds__(256, 2)
void gemm_in(const float* __restrict__ X,
             const float* __restrict__ Wf, const float* __restrict__ bf,
             const float* __restrict__ Ws, const float* __restrict__ bs) {
    __shared__ ull   sA[BK][BM + 2];
    __shared__ float sB[BK][BN];

    const int tid = threadIdx.x;
    const int which = blockIdx.y;
    const float* W    = (which < 2) ? Wf : Ws;
    const float* bias = (which < 2) ? bf : bs;
    float*       out  = (which < 2) ? g_xf : g_xs;
    const int    n0   = (which & 1) * BN;
    const size_t m0   = (size_t)blockIdx.x * BM;

    const int tx = tid & 15;
    const int ty = tid >> 4;

    ull acc[8][4];
#pragma unroll
    for (int i = 0; i < 8; i++)
#pragma unroll
        for (int j = 0; j < 4; j++) acc[i][j] = 0ull;

    for (int k0 = 0; k0 < IND; k0 += BK) {
#pragma unroll
        for (int it = 0; it < 2; it++) {
            int s   = tid + it * 256;
            int row = s >> 2;
            int kq  = (s & 3) * 4;
            float4 v = *(const float4*)&X[(m0 + row) * IND + k0 + kq];
            sA[kq + 0][row] = pack2(v.x, v.x);
            sA[kq + 1][row] = pack2(v.y, v.y);
            sA[kq + 2][row] = pack2(v.z, v.z);
            sA[kq + 3][row] = pack2(v.w, v.w);
        }
#pragma unroll
        for (int it = 0; it < 2; it++) {
            int s  = tid + it * 256;
            int kr = s >> 5;
            int nq = (s & 31) * 4;
            *(float4*)&sB[kr][nq] =
                *(const float4*)&W[(size_t)(k0 + kr) * UNITS + n0 + nq];
        }
        __syncthreads();

#pragma unroll
        for (int k = 0; k < BK; k++) {
            ull a[8];
#pragma unroll
            for (int i = 0; i < 8; i++) a[i] = sA[k][ty * 8 + i];
            const ull* b2 = (const ull*)&sB[k][tx * 8];
            ull b[4];
#pragma unroll
            for (int j = 0; j < 4; j++) b[j] = b2[j];
#pragma unroll
            for (int i = 0; i < 8; i++)
#pragma unroll
                for (int j = 0; j < 4; j++) fma2(acc[i][j], a[i], b[j]);
        }
        __syncthreads();
    }

    float bv[8];
#pragma unroll
    for (int j = 0; j < 8; j++) bv[j] = bias[n0 + tx * 8 + j];
#pragma unroll
    for (int i = 0; i < 8; i++) {
        size_t row = m0 + ty * 8 + i;
        float2 r0 = unpack2(acc[i][0]);
        float2 r1 = unpack2(acc[i][1]);
        float2 r2 = unpack2(acc[i][2]);
        float2 r3 = unpack2(acc[i][3]);
        float4 o0 = make_float4(r0.x + bv[0], r0.y + bv[1],
                                r1.x + bv[2], r1.y + bv[3]);
        float4 o1 = make_float4(r2.x + bv[4], r2.y + bv[5],
                                r3.x + bv[6], r3.y + bv[7]);
        *(float4*)&out[row * UNITS + n0 + tx * 8]     = o0;
        *(float4*)&out[row * UNITS + n0 + tx * 8 + 4] = o1;
    }
}

// ---------------------------------------------------------------------------
// Phase 2: cluster-2 scan, TWO batch rows per cluster (ILP), flag handshake.
// 64 CTAs (32 clusters). Thread = (unit uL = t>>1, k-half kh = t&1).
// Per thread per matrix (over its 128-wide k-half): 36 pairs RF, 28 pairs smem.
// Weights shared across both rows; 8 independent FMA chains per thread.
// ---------------------------------------------------------------------------
#define RF_S 18                               // RF vh-slots (36 pairs)
#define SW_J 14                               // smem vh-slots (28 pairs)
#define SW_BYTES (SW_J * 256 * 16)            // 57344 per matrix
#define VEC_BYTES 1088                        // 256 floats + 16B skew + pad
#define SH_OFF   (2 * SW_BYTES)               // 114688
#define FLG_OFF  (SH_OFF + 4 * VEC_BYTES)
#define SMEM_SCAN (FLG_OFF + 64)              // 119104 bytes

__device__ __forceinline__ uint32_t ctarank() {
    uint32_t r;
    asm("mov.u32 %0, %%cluster_ctarank;" : "=r"(r));
    return r;
}
__device__ __forceinline__ uint32_t mapa_addr(const void* laddr, uint32_t peer) {
    uint32_t la = (uint32_t)__cvta_generic_to_shared(laddr);
    uint32_t ra;
    asm("mapa.shared::cluster.u32 %0, %1, %2;" : "=r"(ra) : "r"(la), "r"(peer));
    return ra;
}
__device__ __forceinline__ void st_rlx_remote(uint32_t ra, float v) {
    asm volatile("st.relaxed.cluster.shared::cluster.b32 [%0], %1;"
                 :: "r"(ra), "r"(__float_as_uint(v)) : "memory");
}
__device__ __forceinline__ void st_rel_remote(uint32_t ra, uint32_t v) {
    asm volatile("st.release.cluster.shared::cluster.b32 [%0], %1;"
                 :: "r"(ra), "r"(v) : "memory");
}
__device__ __forceinline__ uint32_t ld_acq_local(const uint32_t* p) {
    uint32_t la = (uint32_t)__cvta_generic_to_shared(p);
    uint32_t v;
    asm volatile("ld.acquire.cluster.shared::cta.b32 %0, [%1];"
                 : "=r"(v) : "r"(la) : "memory");
    return v;
}
__device__ __forceinline__ void spin_ge(const uint32_t* flag, uint32_t want) {
    while (ld_acq_local(flag) < want) {}
}

// Dual-row partial dot over a 128-wide k-half.
__device__ __forceinline__ void matvec2(const ulonglong2* __restrict__ vh0,
                                        const ulonglong2* __restrict__ vh1,
                                        const ull (&rW)[2 * RF_S],
                                        const ulonglong2* __restrict__ sW,
                                        int t, float& r0, float& r1) {
    ull a0 = 0, a1 = 0, a2 = 0, a3 = 0;     // row 0 chains
    ull c0 = 0, c1 = 0, c2 = 0, c3 = 0;     // row 1 chains
#pragma unroll
    for (int j = 0; j < RF_S; j++) {
        ulonglong2 h0 = vh0[j];
        ulonglong2 h1 = vh1[j];
        fma2(a0, h0.x, rW[2 * j]);
        fma2(a1, h0.y, rW[2 * j + 1]);
        fma2(c0, h1.x, rW[2 * j]);
        fma2(c1, h1.y, rW[2 * j + 1]);
    }
#pragma unroll
    for (int j = 0; j < SW_J; j++) {
        ulonglong2 wv = sW[j * 256 + t];
        ulonglong2 h0 = vh0[RF_S + j];
        ulonglong2 h1 = vh1[RF_S + j];
        fma2(a2, h0.x, wv.x);
        fma2(a3, h0.y, wv.y);
        fma2(c2, h1.x, wv.x);
        fma2(c3, h1.y, wv.y);
    }
    add2(a0, a1); add2(a2, a3); add2(a0, a2);
    add2(c0, c1); add2(c2, c3); add2(c0, c2);
    float2 x0 = unpack2(a0);
    float2 x1 = unpack2(c0);
    r0 = x0.x + x0.y;
    r1 = x1.x + x1.y;
}

__global__ __launch_bounds__(256, 1) __cluster_dims__(2, 1, 1)
void mgu_scan(const float* __restrict__ Uf, const float* __restrict__ Us,
              float* __restrict__ out) {
    extern __shared__ char smem[];
    ulonglong2* sWf = (ulonglong2*)smem;                  // [SW_J][256]
    ulonglong2* sWs = (ulonglong2*)(smem + SW_BYTES);
    float* shv0  = (float*)(smem + SH_OFF);               // skewed h row0
    float* sfhv0 = (float*)(smem + SH_OFF + VEC_BYTES);
    float* shv1  = (float*)(smem + SH_OFF + 2 * VEC_BYTES);
    float* sfhv1 = (float*)(smem + SH_OFF + 3 * VEC_BYTES);
    uint32_t* flg = (uint32_t*)(smem + FLG_OFF);          // [0]=H, [8]=FH

    const int t  = threadIdx.x;
    const int uL = t >> 1;
    const int kh = t & 1;
    const uint32_t rank = ctarank();
    const uint32_t peer = rank ^ 1u;
    const int ug = (int)rank * 128 + uL;
    const int c  = blockIdx.x >> 1;           // cluster id (0..31)
    const int b0 = 2 * c, b1 = 2 * c + 1;     // the two batch rows
    const int k0 = kh * 128;

    // ---- RF weight preload: pairs 0..35 -> k = k0 + [0,72) ----
    ull rF[2 * RF_S], rS[2 * RF_S];
#pragma unroll
    for (int p = 0; p < 2 * RF_S; p++) {
        rF[p] = pack2(Uf[(size_t)(k0 + 2 * p)     * UNITS + ug],
                      Uf[(size_t)(k0 + 2 * p + 1) * UNITS + ug]);
        rS[p] = pack2(Us[(size_t)(k0 + 2 * p)     * UNITS + ug],
                      Us[(size_t)(k0 + 2 * p + 1) * UNITS + ug]);
    }
    // ---- smem weight preload: slot j -> k = k0 + 72 + 4j ----
#pragma unroll
    for (int j = 0; j < SW_J; j++) {
        int kk = k0 + 72 + 4 * j;
        sWf[j * 256 + t] = make_ulonglong2(
            pack2(Uf[(size_t)kk       * UNITS + ug], Uf[(size_t)(kk + 1) * UNITS + ug]),
            pack2(Uf[(size_t)(kk + 2) * UNITS + ug], Uf[(size_t)(kk + 3) * UNITS + ug]));
        sWs[j * 256 + t] = make_ulonglong2(
            pack2(Us[(size_t)kk       * UNITS + ug], Us[(size_t)(kk + 1) * UNITS + ug]),
            pack2(Us[(size_t)(kk + 2) * UNITS + ug], Us[(size_t)(kk + 3) * UNITS + ug]));
    }
    // init all 4 vectors (incl. skew pads) + flags
    for (int i = t; i < 4 * (VEC_BYTES / 4); i += 256)
        ((float*)(smem + SH_OFF))[i] = 0.0f;
    if (t == 0) { flg[0] = 0u; flg[8] = 0u; }
    __syncthreads();
    asm volatile("barrier.cluster.arrive.aligned;" ::: "memory");
    asm volatile("barrier.cluster.wait.aligned;"   ::: "memory");

    const int voff = ug + ((int)rank) * 4;    // skewed float offset
    const ulonglong2* vhh0  = (const ulonglong2*)((char*)shv0  + kh * 528);
    const ulonglong2* vhf0  = (const ulonglong2*)((char*)sfhv0 + kh * 528);
    const ulonglong2* vhh1  = (const ulonglong2*)((char*)shv1  + kh * 528);
    const ulonglong2* vhf1  = (const ulonglong2*)((char*)sfhv1 + kh * 528);

    uint32_t ra_fh0 = 0, ra_fh1 = 0, ra_h0 = 0, ra_h1 = 0;
    uint32_t ra_flag_fh = 0, ra_flag_h = 0;
    if (kh == 0) {
        ra_fh0 = mapa_addr(&sfhv0[voff], peer);
        ra_fh1 = mapa_addr(&sfhv1[voff], peer);
        ra_h0  = mapa_addr(&shv0[voff],  peer);
        ra_h1  = mapa_addr(&shv1[voff],  peer);
    }
    if (t == 0) {
        ra_flag_h  = mapa_addr(&flg[0], peer);
        ra_flag_fh = mapa_addr(&flg[8], peer);
    }

    const bool remote_half = (kh != (int)rank);
    float h0 = 0.0f, h1 = 0.0f;
    size_t xo0 = ((size_t)b0 * SEQ) * UNITS + ug;
    size_t xo1 = ((size_t)b1 * SEQ) * UNITS + ug;

    for (int step = 0; step < SEQ; step++) {
        float xf0 = __ldcg(&g_xf[xo0]);
        float xs0 = __ldcg(&g_xs[xo0]);
        float xf1 = __ldcg(&g_xf[xo1]);
        float xs1 = __ldcg(&g_xs[xo1]);

        // ---- matvec 1 (both rows): h @ U_f ----
        if (remote_half) spin_ge(&flg[0], (uint32_t)step);
        float p0, p1;
        matvec2(vhh0, vhh1, rF, sWf, t, p0, p1);
        p0 += __shfl_xor_sync(0xffffffffu, p0, 1);
        p1 += __shfl_xor_sync(0xffffffffu, p1, 1);
        float f0 = 1.0f / (1.0f + __expf(-(xf0 + p0)));
        float f1 = 1.0f / (1.0f + __expf(-(xf1 + p1)));
        float fh0 = f0 * h0;
        float fh1 = f1 * h1;
        if (kh == 0) {
            sfhv0[voff] = fh0; st_rlx_remote(ra_fh0, fh0);
            sfhv1[voff] = fh1; st_rlx_remote(ra_fh1, fh1);
        }
        __syncthreads();                                   // S_a
        if (t == 0) st_rel_remote(ra_flag_fh, (uint32_t)(step + 1));

        // ---- matvec 2 (both rows): (f*h) @ U_s ----
        if (remote_half) spin_ge(&flg[8], (uint32_t)(step + 1));
        float q0, q1;
        matvec2(vhf0, vhf1, rS, sWs, t, q0, q1);
        q0 += __shfl_xor_sync(0xffffffffu, q0, 1);
        q1 += __shfl_xor_sync(0xffffffffu, q1, 1);

        float s0 = xs0 + q0;
        float a0 = fabsf(s0);
        float e0 = __expf(-2.0f * a0);
        float t0 = copysignf((1.0f - e0) / (1.0f + e0), s0);
        float s1 = xs1 + q1;
        float a1 = fabsf(s1);
        float e1 = __expf(-2.0f * a1);
        float t1 = copysignf((1.0f - e1) / (1.0f + e1), s1);

        float hn0 = h0 + f0 * (t0 - h0);                   // (1-f)h + f*th
        float hn1 = h1 + f1 * (t1 - h1);
        if (kh == 0) {
            out[xo0] = hn0;
            out[xo1] = hn1;
            shv0[voff] = hn0; st_rlx_remote(ra_h0, hn0);
            shv1[voff] = hn1; st_rlx_remote(ra_h1, hn1);
        }
        h0 = hn0;
        h1 = hn1;
        xo0 += UNITS;
        xo1 += UNITS;
        __syncthreads();                                   // S_b
        if (t == 0) st_rel_remote(ra_flag_h, (uint32_t)(step + 1));
    }

    // Don't exit while the peer may still write into our smem.
    asm volatile("barrier.cluster.arrive.aligned;" ::: "memory");
    asm volatile("barrier.cluster.wait.aligned;"   ::: "memory");
}

// ---------------------------------------------------------------------------
// Entry point
// ---------------------------------------------------------------------------
extern "C" void kernel_launch(void* const* d_in, const int* in_sizes, int n_in,
                              void* d_out, int out_size) {
    const float* X  = (const float*)d_in[0];
    const float* Wf = (const float*)d_in[1];
    const float* Uf = (const float*)d_in[2];
    const float* bf = (const float*)d_in[3];
    const float* Ws = (const float*)d_in[4];
    const float* Us = (const float*)d_in[5];
    const float* bs = (const float*)d_in[6];
    float* out = (float*)d_out;
    (void)in_sizes; (void)n_in; (void)out_size;

    cudaFuncSetAttribute(mgu_scan,
                         cudaFuncAttributeMaxDynamicSharedMemorySize, SMEM_SCAN);

    gemm_in<<<dim3(M_TOTAL / BM, 4), 256>>>(X, Wf, bf, Ws, bs);
    mgu_scan<<<BATCH, 256, SMEM_SCAN>>>(Uf, Us, out);   // 64 CTAs, 32 clusters
}

// round 14
// speedup vs baseline: 1.7926x; 1.7926x over previous
#include <cuda_runtime.h>
#include <cstdint>
#include <cstddef>

// ---------------------------------------------------------------------------
// Problem dims (fixed)
// ---------------------------------------------------------------------------
#define BATCH 64
#define SEQ   2048
#define IND   256
#define UNITS 256
#define M_TOTAL (BATCH * SEQ)          // 131072

typedef unsigned long long ull;

// ---------------------------------------------------------------------------
// Device-global scratch (padded by UNITS for the x prefetch of the last step)
// ---------------------------------------------------------------------------
__device__ float g_xf[(size_t)M_TOTAL * UNITS + UNITS];
__device__ float g_xs[(size_t)M_TOTAL * UNITS + UNITS];

// ---------------------------------------------------------------------------
// Packed f32x2 helpers
// ---------------------------------------------------------------------------
__device__ __forceinline__ void fma2(ull& d, ull a, ull b) {
    asm("fma.rn.f32x2 %0, %1, %2, %0;" : "+l"(d) : "l"(a), "l"(b));
}
__device__ __forceinline__ void add2(ull& d, ull a) {
    asm("add.rn.f32x2 %0, %0, %1;" : "+l"(d) : "l"(a));
}
__device__ __forceinline__ ull pack2(float x, float y) {
    ull r;
    asm("mov.b64 %0, {%1, %2};" : "=l"(r)
        : "r"(__float_as_uint(x)), "r"(__float_as_uint(y)));
    return r;
}
__device__ __forceinline__ float2 unpack2(ull v) {
    unsigned lo, hi;
    asm("mov.b64 {%0, %1}, %2;" : "=r"(lo), "=r"(hi) : "l"(v));
    return make_float2(__uint_as_float(lo), __uint_as_float(hi));
}

// ---------------------------------------------------------------------------
// Phase 1: xf = X @ W_f + b_f ; xs = X @ W_s + b_s   (unchanged)
// ---------------------------------------------------------------------------
#define BM 128
#define BN 128
#define BK 16

__global__ __launch_bounds__(256, 2)
void gemm_in(const float* __restrict__ X,
             const float* __restrict__ Wf, const float* __restrict__ bf,
             const float* __restrict__ Ws, const float* __restrict__ bs) {
    __shared__ ull   sA[BK][BM + 2];
    __shared__ float sB[BK][BN];

    const int tid = threadIdx.x;
    const int which = blockIdx.y;
    const float* W    = (which < 2) ? Wf : Ws;
    const float* bias = (which < 2) ? bf : bs;
    float*       out  = (which < 2) ? g_xf : g_xs;
    const int    n0   = (which & 1) * BN;
    const size_t m0   = (size_t)blockIdx.x * BM;

    const int tx = tid & 15;
    const int ty = tid >> 4;

    ull acc[8][4];
#pragma unroll
    for (int i = 0; i < 8; i++)
#pragma unroll
        for (int j = 0; j < 4; j++) acc[i][j] = 0ull;

    for (int k0 = 0; k0 < IND; k0 += BK) {
#pragma unroll
        for (int it = 0; it < 2; it++) {
            int s   = tid + it * 256;
            int row = s >> 2;
            int kq  = (s & 3) * 4;
            float4 v = *(const float4*)&X[(m0 + row) * IND + k0 + kq];
            sA[kq + 0][row] = pack2(v.x, v.x);
            sA[kq + 1][row] = pack2(v.y, v.y);
            sA[kq + 2][row] = pack2(v.z, v.z);
            sA[kq + 3][row] = pack2(v.w, v.w);
        }
#pragma unroll
        for (int it = 0; it < 2; it++) {
            int s  = tid + it * 256;
            int kr = s >> 5;
            int nq = (s & 31) * 4;
            *(float4*)&sB[kr][nq] =
                *(const float4*)&W[(size_t)(k0 + kr) * UNITS + n0 + nq];
        }
        __syncthreads();

#pragma unroll
        for (int k = 0; k < BK; k++) {
            ull a[8];
#pragma unroll
            for (int i = 0; i < 8; i++) a[i] = sA[k][ty * 8 + i];
            const ull* b2 = (const ull*)&sB[k][tx * 8];
            ull b[4];
#pragma unroll
            for (int j = 0; j < 4; j++) b[j] = b2[j];
#pragma unroll
            for (int i = 0; i < 8; i++)
#pragma unroll
                for (int j = 0; j < 4; j++) fma2(acc[i][j], a[i], b[j]);
        }
        __syncthreads();
    }

    float bv[8];
#pragma unroll
    for (int j = 0; j < 8; j++) bv[j] = bias[n0 + tx * 8 + j];
#pragma unroll
    for (int i = 0; i < 8; i++) {
        size_t row = m0 + ty * 8 + i;
        float2 r0 = unpack2(acc[i][0]);
        float2 r1 = unpack2(acc[i][1]);
        float2 r2 = unpack2(acc[i][2]);
        float2 r3 = unpack2(acc[i][3]);
        float4 o0 = make_float4(r0.x + bv[0], r0.y + bv[1],
                                r1.x + bv[2], r1.y + bv[3]);
        float4 o1 = make_float4(r2.x + bv[4], r2.y + bv[5],
                                r3.x + bv[6], r3.y + bv[7]);
        *(float4*)&out[row * UNITS + n0 + tx * 8]     = o0;
        *(float4*)&out[row * UNITS + n0 + tx * 8 + 4] = o1;
    }
}

// ---------------------------------------------------------------------------
// Phase 2: cluster-2 scan, ONE row per cluster, interleaved local/remote k.
// 128 CTAs. Thread = (unit uL = t>>1, kh = t&1); lane pair combines via
// shfl.bfly(1). Thread's 128-k range = 64 LOCAL k (own CTA's units, no flag
// needed) + 64 REMOTE k (peer's units, flag-gated). Execution order:
// local RF (8 pairs) -> local smem (24 pairs) -> spin -> remote RF (32 pairs).
// Post-flag tail is pure register FMAs. h/fh vectors skewed 16B per 64 floats
// for conflict-free dual-broadcast LDS.
// ---------------------------------------------------------------------------
#define RFLP 8                                // local RF pairs per matrix
#define RFRP 32                               // remote RF pairs per matrix
#define SW_J 12                               // local smem slots (24 pairs)
#define SW_BYTES (SW_J * 256 * 16)            // 49152 per matrix
#define VEC_BYTES 1088                        // 256 floats + 4x16B skew
#define SH_OFF   (2 * SW_BYTES)               // 98304
#define SFH_OFF  (SH_OFF + VEC_BYTES)
#define FLG_OFF  (SFH_OFF + VEC_BYTES)
#define SMEM_SCAN (FLG_OFF + 64)              // 100608 bytes

__device__ __forceinline__ uint32_t ctarank() {
    uint32_t r;
    asm("mov.u32 %0, %%cluster_ctarank;" : "=r"(r));
    return r;
}
__device__ __forceinline__ uint32_t mapa_addr(const void* laddr, uint32_t peer) {
    uint32_t la = (uint32_t)__cvta_generic_to_shared(laddr);
    uint32_t ra;
    asm("mapa.shared::cluster.u32 %0, %1, %2;" : "=r"(ra) : "r"(la), "r"(peer));
    return ra;
}
__device__ __forceinline__ void st_rlx_remote(uint32_t ra, float v) {
    asm volatile("st.relaxed.cluster.shared::cluster.b32 [%0], %1;"
                 :: "r"(ra), "r"(__float_as_uint(v)) : "memory");
}
__device__ __forceinline__ void st_rel_remote(uint32_t ra, uint32_t v) {
    asm volatile("st.release.cluster.shared::cluster.b32 [%0], %1;"
                 :: "r"(ra), "r"(v) : "memory");
}
__device__ __forceinline__ uint32_t ld_acq_local(const uint32_t* p) {
    uint32_t la = (uint32_t)__cvta_generic_to_shared(p);
    uint32_t v;
    asm volatile("ld.acquire.cluster.shared::cta.b32 %0, [%1];"
                 : "=r"(v) : "r"(la) : "memory");
    return v;
}
__device__ __forceinline__ void spin_ge(const uint32_t* flag, uint32_t want) {
    while (ld_acq_local(flag) < want) {}
}

__global__ __launch_bounds__(256, 1) __cluster_dims__(2, 1, 1)
void mgu_scan(const float* __restrict__ Uf, const float* __restrict__ Us,
              float* __restrict__ out) {
    extern __shared__ char smem[];
    ulonglong2* sWf = (ulonglong2*)smem;                  // [SW_J][256]
    ulonglong2* sWs = (ulonglong2*)(smem + SW_BYTES);
    char* vh  = smem + SH_OFF;                            // skewed h vector
    char* vfh = smem + SFH_OFF;                           // skewed f*h vector
    uint32_t* flg = (uint32_t*)(smem + FLG_OFF);          // [0]=H, [8]=FH

    const int t  = threadIdx.x;
    const int uL = t >> 1;
    const int kh = t & 1;
    const uint32_t rank = ctarank();
    const uint32_t peer = rank ^ 1u;
    const int ug = (int)rank * 128 + uL;      // this thread's unit
    const int b  = blockIdx.x >> 1;           // batch row
    const int Lb = (int)rank * 128 + kh * 64; // local-k base (own CTA produces)
    const int Rb = (int)peer * 128 + kh * 64; // remote-k base (peer produces)

    // ---- RF preload: local pairs 0..7 (k = Lb..Lb+15), remote pairs 0..31 ----
    ull rFl[RFLP], rSl[RFLP], rFr[RFRP], rSr[RFRP];
#pragma unroll
    for (int p = 0; p < RFLP; p++) {
        int k = Lb + 2 * p;
        rFl[p] = pack2(Uf[(size_t)k * UNITS + ug], Uf[(size_t)(k + 1) * UNITS + ug]);
        rSl[p] = pack2(Us[(size_t)k * UNITS + ug], Us[(size_t)(k + 1) * UNITS + ug]);
    }
#pragma unroll
    for (int p = 0; p < RFRP; p++) {
        int k = Rb + 2 * p;
        rFr[p] = pack2(Uf[(size_t)k * UNITS + ug], Uf[(size_t)(k + 1) * UNITS + ug]);
        rSr[p] = pack2(Us[(size_t)k * UNITS + ug], Us[(size_t)(k + 1) * UNITS + ug]);
    }
    // ---- smem preload: slot j -> local k = Lb + 16 + 4j ----
#pragma unroll
    for (int j = 0; j < SW_J; j++) {
        int kk = Lb + 16 + 4 * j;
        sWf[j * 256 + t] = make_ulonglong2(
            pack2(Uf[(size_t)kk       * UNITS + ug], Uf[(size_t)(kk + 1) * UNITS + ug]),
            pack2(Uf[(size_t)(kk + 2) * UNITS + ug], Uf[(size_t)(kk + 3) * UNITS + ug]));
        sWs[j * 256 + t] = make_ulonglong2(
            pack2(Us[(size_t)kk       * UNITS + ug], Us[(size_t)(kk + 1) * UNITS + ug]),
            pack2(Us[(size_t)(kk + 2) * UNITS + ug], Us[(size_t)(kk + 3) * UNITS + ug]));
    }
    // zero both vectors (incl. skew pads) + flags
    for (int i = t; i < 2 * VEC_BYTES / 4; i += 256)
        ((float*)(smem + SH_OFF))[i] = 0.0f;
    if (t == 0) { flg[0] = 0u; flg[8] = 0u; }
    __syncthreads();
    asm volatile("barrier.cluster.arrive.aligned;" ::: "memory");
    asm volatile("barrier.cluster.wait.aligned;"   ::: "memory");

    // Skewed addressing: addr(f) = f*4 + (f>>6)*16
    const int addrL = Lb * 4 + (Lb >> 6) * 16;
    const int addrR = Rb * 4 + (Rb >> 6) * 16;
    const ulonglong2* vhL  = (const ulonglong2*)(vh  + addrL);  // 16 slots
    const ulonglong2* vhR  = (const ulonglong2*)(vh  + addrR);
    const ulonglong2* vfhL = (const ulonglong2*)(vfh + addrL);
    const ulonglong2* vfhR = (const ulonglong2*)(vfh + addrR);
    const int aU = ug * 4 + (ug >> 6) * 16;
    float* myh  = (float*)(vh  + aU);
    float* myfh = (float*)(vfh + aU);

    uint32_t ra_fh = 0, ra_h = 0, ra_flag_fh = 0, ra_flag_h = 0;
    if (kh == 0) {
        ra_fh = mapa_addr(myfh, peer);
        ra_h  = mapa_addr(myh,  peer);
    }
    if (t == 0) {
        ra_flag_h  = mapa_addr(&flg[0], peer);
        ra_flag_fh = mapa_addr(&flg[8], peer);
    }

    float h_reg = 0.0f;
    size_t xo = ((size_t)b * SEQ) * UNITS + ug;
    float xf_c = __ldcg(&g_xf[xo]);
    float xs_c = __ldcg(&g_xs[xo]);

    for (int step = 0; step < SEQ; step++) {
        // prefetch next step's x (full-step latency cover; padded arrays)
        float xf_n = __ldcg(&g_xf[xo + UNITS]);
        float xs_n = __ldcg(&g_xs[xo + UNITS]);

        // ======== phase 1: h @ U_f ========
        ull a0 = 0, a1 = 0, a2 = 0, a3 = 0;
#pragma unroll
        for (int j = 0; j < 4; j++) {               // local RF (8 pairs)
            ulonglong2 hv = vhL[j];
            fma2(a0, hv.x, rFl[2 * j]);
            fma2(a1, hv.y, rFl[2 * j + 1]);
        }
#pragma unroll
        for (int j = 0; j < SW_J; j++) {            // local smem (24 pairs)
            ulonglong2 hv = vhL[4 + j];
            ulonglong2 wv = sWf[j * 256 + t];
            fma2(a2, hv.x, wv.x);
            fma2(a3, hv.y, wv.y);
        }
        spin_ge(&flg[0], (uint32_t)step);           // remote h ready?
#pragma unroll
        for (int j = 0; j < 16; j++) {              // remote RF (32 pairs)
            ulonglong2 hv = vhR[j];
            fma2(a0, hv.x, rFr[2 * j]);
            fma2(a1, hv.y, rFr[2 * j + 1]);
        }
        add2(a0, a1); add2(a2, a3); add2(a0, a2);
        float2 rr = unpack2(a0);
        float p = rr.x + rr.y;
        p += __shfl_xor_sync(0xffffffffu, p, 1);
        float f  = 1.0f / (1.0f + __expf(-(xf_c + p)));
        float fh = f * h_reg;
        if (kh == 0) { st_rlx_remote(ra_fh, fh); *myfh = fh; }
        __syncthreads();                                       // S_a
        if (t == 0) st_rel_remote(ra_flag_fh, (uint32_t)(step + 1));

        // ======== phase 2: (f*h) @ U_s ========
        a0 = 0; a1 = 0; a2 = 0; a3 = 0;
#pragma unroll
        for (int j = 0; j < 4; j++) {               // local RF
            ulonglong2 hv = vfhL[j];
            fma2(a0, hv.x, rSl[2 * j]);
            fma2(a1, hv.y, rSl[2 * j + 1]);
        }
#pragma unroll
        for (int j = 0; j < SW_J; j++) {            // local smem
            ulonglong2 hv = vfhL[4 + j];
            ulonglong2 wv = sWs[j * 256 + t];
            fma2(a2, hv.x, wv.x);
            fma2(a3, hv.y, wv.y);
        }
        spin_ge(&flg[8], (uint32_t)(step + 1));     // remote fh ready?
#pragma unroll
        for (int j = 0; j < 16; j++) {              // remote RF
            ulonglong2 hv = vfhR[j];
            fma2(a0, hv.x, rSr[2 * j]);
            fma2(a1, hv.y, rSr[2 * j + 1]);
        }
        add2(a0, a1); add2(a2, a3); add2(a0, a2);
        float2 qq = unpack2(a0);
        float q = qq.x + qq.y;
        q += __shfl_xor_sync(0xffffffffu, q, 1);

        float s  = xs_c + q;
        float ax = fabsf(s);
        float e  = __expf(-2.0f * ax);
        float th = copysignf((1.0f - e) / (1.0f + e), s);      // safe tanh

        float hn = h_reg + f * (th - h_reg);                   // (1-f)h + f*th
        if (kh == 0) {
            out[xo] = hn;
            st_rlx_remote(ra_h, hn);
            *myh = hn;
        }
        h_reg = hn;
        xf_c = xf_n;
        xs_c = xs_n;
        xo += UNITS;
        __syncthreads();                                       // S_b
        if (t == 0) st_rel_remote(ra_flag_h, (uint32_t)(step + 1));
    }

    // Don't exit while the peer may still write into our smem.
    asm volatile("barrier.cluster.arrive.aligned;" ::: "memory");
    asm volatile("barrier.cluster.wait.aligned;"   ::: "memory");
}

// ---------------------------------------------------------------------------
// Entry point
// ---------------------------------------------------------------------------
extern "C" void kernel_launch(void* const* d_in, const int* in_sizes, int n_in,
                              void* d_out, int out_size) {
    const float* X  = (const float*)d_in[0];
    const float* Wf = (const float*)d_in[1];
    const float* Uf = (const float*)d_in[2];
    const float* bf = (const float*)d_in[3];
    const float* Ws = (const float*)d_in[4];
    const float* Us = (const float*)d_in[5];
    const float* bs = (const float*)d_in[6];
    float* out = (float*)d_out;
    (void)in_sizes; (void)n_in; (void)out_size;

    cudaFuncSetAttribute(mgu_scan,
                         cudaFuncAttributeMaxDynamicSharedMemorySize, SMEM_SCAN);

    gemm_in<<<dim3(M_TOTAL / BM, 4), 256>>>(X, Wf, bf, Ws, bs);
    mgu_scan<<<2 * BATCH, 256, SMEM_SCAN>>>(Uf, Us, out);
}